// round 6
// baseline (speedup 1.0000x reference)
#include <cuda_runtime.h>
#include <stdint.h>

#define NN 50000
#define EE 320000
#define FF 256
#define KK 2

// Scratch (allocation-free rule: __device__ globals)
__device__ float g_h[(size_t)KK * NN * FF];    // h[k,n,f] = x @ init_weight[k]
__device__ float g_acc[(size_t)KK * NN * FF];  // root[k] + bias (gemm writes here)
__device__ int   g_degi[NN];
__device__ float g_dinv[NN];
__device__ int   g_rowstart[NN + 1];
__device__ int   g_cursor[NN];
__device__ int   g_csr_src[EE];
__device__ float g_csr_w[EE];
__device__ int   g_is64;   // 1 if edge_index buffer is int64, 0 if int32

// ---------------------------------------------------------------------------
// dtype sniff: int64 edge_index (values < 2^31) has ALL odd 32-bit words == 0.
// int32 edge_index has random node ids there -> impossible for 256 to be 0.
// ---------------------------------------------------------------------------
__global__ void sniff_kernel(const int* __restrict__ ei32) {
    if (threadIdx.x == 0) {
        int any = 0;
        for (int i = 0; i < 256; ++i) any |= ei32[2 * i + 1];
        g_is64 = (any == 0) ? 1 : 0;
    }
}

__device__ __forceinline__ int load_idx(const void* ei, int which, int e) {
    if (g_is64) return (int)((const long long*)ei)[(size_t)which * EE + e];
    return ((const int*)ei)[(size_t)which * EE + e];
}

// ---------------------------------------------------------------------------
// degree
// ---------------------------------------------------------------------------
__global__ void zero_deg_kernel() {
    int i = blockIdx.x * blockDim.x + threadIdx.x;
    if (i < NN) g_degi[i] = 0;
}

__global__ void deg_kernel(const void* __restrict__ ei) {
    int e = blockIdx.x * blockDim.x + threadIdx.x;
    if (e < EE) {
        int dst = load_idx(ei, 1, e);
        atomicAdd(&g_degi[dst], 1);
    }
}

__global__ void dinv_kernel() {
    int i = blockIdx.x * blockDim.x + threadIdx.x;
    if (i < NN) {
        int d = g_degi[i];
        g_dinv[i] = (d > 0) ? rsqrtf((float)d) : 0.0f;
    }
}

// ---------------------------------------------------------------------------
// Exclusive scan of g_degi -> g_rowstart, single block of 1024 threads.
// ---------------------------------------------------------------------------
#define SCAN_CH 49  // 1024 * 49 = 50176 >= NN

__global__ __launch_bounds__(1024) void scan_kernel() {
    __shared__ int s[1024];
    const int t = threadIdx.x;
    const int base = t * SCAN_CH;

    int sum = 0;
#pragma unroll
    for (int i = 0; i < SCAN_CH; ++i) {
        int idx = base + i;
        if (idx < NN) sum += g_degi[idx];
    }
    s[t] = sum;
    __syncthreads();

    for (int off = 1; off < 1024; off <<= 1) {
        int v = (t >= off) ? s[t - off] : 0;
        __syncthreads();
        s[t] += v;
        __syncthreads();
    }

    int run = (t == 0) ? 0 : s[t - 1];
#pragma unroll
    for (int i = 0; i < SCAN_CH; ++i) {
        int idx = base + i;
        if (idx < NN) {
            g_rowstart[idx] = run;
            run += g_degi[idx];
            g_cursor[idx] = 0;
        }
    }
    if (t == 1023) g_rowstart[NN] = run;
}

// ---------------------------------------------------------------------------
// CSR fill (int atomics only)
// ---------------------------------------------------------------------------
__global__ void fill_csr_kernel(const void* __restrict__ ei) {
    int e = blockIdx.x * blockDim.x + threadIdx.x;
    if (e >= EE) return;
    int src = load_idx(ei, 0, e);
    int dst = load_idx(ei, 1, e);
    int pos = atomicAdd(&g_cursor[dst], 1);
    int idx = g_rowstart[dst] + pos;
    g_csr_src[idx] = src;
    g_csr_w[idx] = g_dinv[src] * g_dinv[dst];
}

// ---------------------------------------------------------------------------
// GEMM: cols [0,512) -> g_h (k=0,1), cols [512,1024) -> g_acc (root k=0,1)
// 64x64 tile, BK=16, 256 threads, 4x4 per thread, fp32.
// ---------------------------------------------------------------------------
#define BM 64
#define BN 64
#define BK 16

__global__ __launch_bounds__(256) void gemm_kernel(
    const float* __restrict__ x, const float* __restrict__ wi,
    const float* __restrict__ wr, const float* __restrict__ bias)
{
    __shared__ float As[BK][BM];
    __shared__ float Bs[BK][BN];

    const int tid = threadIdx.x;
    const int tileRow = blockIdx.y * BM;
    const int gcol = blockIdx.x * BN;        // 0..960
    const int mat = gcol >> 8;               // 0,1 -> init; 2,3 -> root
    const int colInMat = gcol & 255;
    const float* B = (mat < 2) ? (wi + (size_t)mat * FF * FF)
                               : (wr + (size_t)(mat - 2) * FF * FF);

    const int tx = tid & 15;
    const int ty = tid >> 4;

    const int ar = tid >> 2;                 // A row in tile 0..63
    const int ac = (tid & 3) * 4;            // A k-offset
    const int br = tid >> 4;                 // B k-row 0..15
    const int bc = (tid & 15) * 4;           // B col

    const bool aValid = (tileRow + ar) < NN;
    const float* aPtr = x + (size_t)(tileRow + ar) * FF + ac;

    float acc[4][4] = {};

    for (int kk = 0; kk < FF; kk += BK) {
        float4 a4 = aValid ? *(const float4*)(aPtr + kk)
                           : make_float4(0.f, 0.f, 0.f, 0.f);
        As[ac + 0][ar] = a4.x;
        As[ac + 1][ar] = a4.y;
        As[ac + 2][ar] = a4.z;
        As[ac + 3][ar] = a4.w;
        float4 b4 = *(const float4*)(B + (size_t)(kk + br) * FF + colInMat + bc);
        *(float4*)&Bs[br][bc] = b4;
        __syncthreads();

#pragma unroll
        for (int k = 0; k < BK; ++k) {
            float4 av = *(const float4*)&As[k][ty * 4];
            float4 bv = *(const float4*)&Bs[k][tx * 4];
            float a_[4] = {av.x, av.y, av.z, av.w};
            float b_[4] = {bv.x, bv.y, bv.z, bv.w};
#pragma unroll
            for (int i = 0; i < 4; ++i)
#pragma unroll
                for (int j = 0; j < 4; ++j)
                    acc[i][j] += a_[i] * b_[j];
        }
        __syncthreads();
    }

    float* out = (mat < 2) ? (g_h + (size_t)mat * NN * FF)
                           : (g_acc + (size_t)(mat - 2) * NN * FF);
    const int col = colInMat + tx * 4;
    float4 badd = make_float4(0.f, 0.f, 0.f, 0.f);
    if (mat >= 2) {
        const float* bptr = bias + (size_t)(mat - 2) * FF + col;
        badd = make_float4(bptr[0], bptr[1], bptr[2], bptr[3]);
    }
#pragma unroll
    for (int i = 0; i < 4; ++i) {
        int row = tileRow + ty * 4 + i;
        if (row < NN) {
            float4 v;
            v.x = acc[i][0] + badd.x;
            v.y = acc[i][1] + badd.y;
            v.z = acc[i][2] + badd.z;
            v.w = acc[i][3] + badd.w;
            *(float4*)(out + (size_t)row * FF + col) = v;
        }
    }
}

// ---------------------------------------------------------------------------
// Gather + fused epilogue: one warp per dst node, no atomics.
// out[n,:] = x[n,:] + relu( 0.5*(relu(agg0+root0) + relu(agg1+root1)) )
// ---------------------------------------------------------------------------
__global__ __launch_bounds__(256) void gather_kernel(
    const float* __restrict__ x, float* __restrict__ out)
{
    const int warp = (blockIdx.x * blockDim.x + threadIdx.x) >> 5;
    const int lane = threadIdx.x & 31;
    if (warp >= NN) return;
    const int n = warp;
    const int f = lane * 8;

    const float* r0 = g_acc + (size_t)n * FF + f;
    const float* r1 = g_acc + ((size_t)NN + n) * FF + f;
    float4 a0 = *(const float4*)(r0);
    float4 a1 = *(const float4*)(r0 + 4);
    float4 b0 = *(const float4*)(r1);
    float4 b1 = *(const float4*)(r1 + 4);

    const int beg = g_rowstart[n];
    const int end = g_rowstart[n + 1];
    for (int e = beg; e < end; ++e) {
        const int src = g_csr_src[e];
        const float w = g_csr_w[e];
        const float* h0 = g_h + (size_t)src * FF + f;
        const float* h1 = g_h + ((size_t)NN + src) * FF + f;
        float4 v;
        v = *(const float4*)(h0);
        a0.x += w * v.x; a0.y += w * v.y; a0.z += w * v.z; a0.w += w * v.w;
        v = *(const float4*)(h0 + 4);
        a1.x += w * v.x; a1.y += w * v.y; a1.z += w * v.z; a1.w += w * v.w;
        v = *(const float4*)(h1);
        b0.x += w * v.x; b0.y += w * v.y; b0.z += w * v.z; b0.w += w * v.w;
        v = *(const float4*)(h1 + 4);
        b1.x += w * v.x; b1.y += w * v.y; b1.z += w * v.z; b1.w += w * v.w;
    }

    const float* xp = x + (size_t)n * FF + f;
    float4 x0 = *(const float4*)(xp);
    float4 x1 = *(const float4*)(xp + 4);
    float4 o0, o1;
    o0.x = x0.x + fmaxf(0.f, 0.5f * (fmaxf(a0.x, 0.f) + fmaxf(b0.x, 0.f)));
    o0.y = x0.y + fmaxf(0.f, 0.5f * (fmaxf(a0.y, 0.f) + fmaxf(b0.y, 0.f)));
    o0.z = x0.z + fmaxf(0.f, 0.5f * (fmaxf(a0.z, 0.f) + fmaxf(b0.z, 0.f)));
    o0.w = x0.w + fmaxf(0.f, 0.5f * (fmaxf(a0.w, 0.f) + fmaxf(b0.w, 0.f)));
    o1.x = x1.x + fmaxf(0.f, 0.5f * (fmaxf(a1.x, 0.f) + fmaxf(b1.x, 0.f)));
    o1.y = x1.y + fmaxf(0.f, 0.5f * (fmaxf(a1.y, 0.f) + fmaxf(b1.y, 0.f)));
    o1.z = x1.z + fmaxf(0.f, 0.5f * (fmaxf(a1.z, 0.f) + fmaxf(b1.z, 0.f)));
    o1.w = x1.w + fmaxf(0.f, 0.5f * (fmaxf(a1.w, 0.f) + fmaxf(b1.w, 0.f)));
    float* op = out + (size_t)n * FF + f;
    *(float4*)(op) = o0;
    *(float4*)(op + 4) = o1;
}

// ---------------------------------------------------------------------------
// launch
// ---------------------------------------------------------------------------
extern "C" void kernel_launch(void* const* d_in, const int* in_sizes, int n_in,
                              void* d_out, int out_size) {
    const float* x    = (const float*)d_in[0];
    const void* ei    = d_in[1];                 // edge_index [2,E], int32 OR int64
    const float* wi   = (const float*)d_in[2];   // [K, F, F]
    const float* wr   = (const float*)d_in[3];   // [K, F, F]
    const float* bias = (const float*)d_in[4];   // [K, 1, F]
    float* out        = (float*)d_out;

    sniff_kernel<<<1, 32>>>((const int*)ei);
    zero_deg_kernel<<<(NN + 255) / 256, 256>>>();
    deg_kernel<<<(EE + 255) / 256, 256>>>(ei);
    dinv_kernel<<<(NN + 255) / 256, 256>>>();
    scan_kernel<<<1, 1024>>>();
    fill_csr_kernel<<<(EE + 255) / 256, 256>>>(ei);

    dim3 ggrid((4 * FF) / BN, (NN + BM - 1) / BM);
    gemm_kernel<<<ggrid, 256>>>(x, wi, wr, bias);

    gather_kernel<<<(NN * 32 + 255) / 256, 256>>>(x, out);
}

// round 7
// speedup vs baseline: 2.1752x; 2.1752x over previous
#include <cuda_runtime.h>
#include <stdint.h>

#define NN 50000
#define EE 320000
#define FF 256
#define KK 2
#define KDIM 512   // fused K: [xp | x] against [Wi_k ; Wr_k]

// Scratch (allocation-free rule: __device__ globals)
__device__ float g_xp[(size_t)NN * FF];   // xp = A_hat @ x
__device__ int   g_degi[NN];
__device__ float g_dinv[NN];
__device__ int   g_rowstart[NN + 1];
__device__ int   g_cursor[NN];
__device__ int   g_csr_src[EE];
__device__ float g_csr_w[EE];
__device__ int   g_is64;

// ---------------------------------------------------------------------------
// dtype sniff: int64 edge_index (values < 2^31) has ALL odd 32-bit words == 0.
// ---------------------------------------------------------------------------
__global__ void sniff_kernel(const int* __restrict__ ei32) {
    if (threadIdx.x == 0) {
        int any = 0;
        for (int i = 0; i < 256; ++i) any |= ei32[2 * i + 1];
        g_is64 = (any == 0) ? 1 : 0;
    }
}

__device__ __forceinline__ int load_idx(const void* ei, int which, int e) {
    if (g_is64) return (int)((const long long*)ei)[(size_t)which * EE + e];
    return ((const int*)ei)[(size_t)which * EE + e];
}

// ---------------------------------------------------------------------------
// degree / dinv
// ---------------------------------------------------------------------------
__global__ void zero_deg_kernel() {
    int i = blockIdx.x * blockDim.x + threadIdx.x;
    if (i < NN) g_degi[i] = 0;
}

__global__ void deg_kernel(const void* __restrict__ ei) {
    int e = blockIdx.x * blockDim.x + threadIdx.x;
    if (e < EE) atomicAdd(&g_degi[load_idx(ei, 1, e)], 1);
}

__global__ void dinv_kernel() {
    int i = blockIdx.x * blockDim.x + threadIdx.x;
    if (i < NN) {
        int d = g_degi[i];
        g_dinv[i] = (d > 0) ? rsqrtf((float)d) : 0.0f;
    }
}

// ---------------------------------------------------------------------------
// Exclusive scan of degrees -> rowstart (one 1024-thread block)
// ---------------------------------------------------------------------------
#define SCAN_CH 49

__global__ __launch_bounds__(1024) void scan_kernel() {
    __shared__ int s[1024];
    const int t = threadIdx.x;
    const int base = t * SCAN_CH;
    int sum = 0;
#pragma unroll
    for (int i = 0; i < SCAN_CH; ++i) {
        int idx = base + i;
        if (idx < NN) sum += g_degi[idx];
    }
    s[t] = sum;
    __syncthreads();
    for (int off = 1; off < 1024; off <<= 1) {
        int v = (t >= off) ? s[t - off] : 0;
        __syncthreads();
        s[t] += v;
        __syncthreads();
    }
    int run = (t == 0) ? 0 : s[t - 1];
#pragma unroll
    for (int i = 0; i < SCAN_CH; ++i) {
        int idx = base + i;
        if (idx < NN) {
            g_rowstart[idx] = run;
            run += g_degi[idx];
            g_cursor[idx] = 0;
        }
    }
    if (t == 1023) g_rowstart[NN] = run;
}

__global__ void fill_csr_kernel(const void* __restrict__ ei) {
    int e = blockIdx.x * blockDim.x + threadIdx.x;
    if (e >= EE) return;
    int src = load_idx(ei, 0, e);
    int dst = load_idx(ei, 1, e);
    int pos = atomicAdd(&g_cursor[dst], 1);
    int idx = g_rowstart[dst] + pos;
    g_csr_src[idx] = src;
    g_csr_w[idx] = g_dinv[src] * g_dinv[dst];
}

// ---------------------------------------------------------------------------
// xp = A_hat @ x : one warp per dst node, no atomics (warp owns its row).
// ---------------------------------------------------------------------------
__global__ __launch_bounds__(256) void gather_xp_kernel(const float* __restrict__ x) {
    const int warp = (blockIdx.x * blockDim.x + threadIdx.x) >> 5;
    const int lane = threadIdx.x & 31;
    if (warp >= NN) return;
    const int n = warp;
    const int f = lane * 8;

    float4 a0 = make_float4(0.f, 0.f, 0.f, 0.f);
    float4 a1 = make_float4(0.f, 0.f, 0.f, 0.f);

    const int beg = g_rowstart[n];
    const int end = g_rowstart[n + 1];
    for (int e = beg; e < end; ++e) {
        const int src = g_csr_src[e];
        const float w = g_csr_w[e];
        const float* xs = x + (size_t)src * FF + f;
        float4 v = *(const float4*)(xs);
        a0.x += w * v.x; a0.y += w * v.y; a0.z += w * v.z; a0.w += w * v.w;
        v = *(const float4*)(xs + 4);
        a1.x += w * v.x; a1.y += w * v.y; a1.z += w * v.z; a1.w += w * v.w;
    }
    float* op = g_xp + (size_t)n * FF + f;
    *(float4*)(op) = a0;
    *(float4*)(op + 4) = a1;
}

// ---------------------------------------------------------------------------
// Fused tf32 tensor-core GEMM + epilogue.
// C_k[n, g] = sum_{f<256} xp[n,f] Wi_k[f,g] + sum_{f<256} x[n,f] Wr_k[f,g]
// out[n, g] = x[n,g] + relu( 0.5*(relu(C_0+b_0) + relu(C_1+b_1)) )
// Tile: 128(M) x 64(N) x 32(K) per iter, both k-matrices accumulated in-block.
// 256 threads = 8 warps (4 over M, 2 over N); warp tile 32x32 per k-matrix.
// ---------------------------------------------------------------------------
__device__ __forceinline__ uint32_t f2tf32(float f) {
    uint32_t r;
    asm("cvt.rna.tf32.f32 %0, %1;" : "=r"(r) : "f"(f));
    return r;
}

__device__ __forceinline__ void mma_tf32(float* c, const uint32_t* a, const uint32_t* b) {
    asm volatile(
        "mma.sync.aligned.m16n8k8.row.col.f32.tf32.tf32.f32 "
        "{%0,%1,%2,%3}, {%4,%5,%6,%7}, {%8,%9}, {%0,%1,%2,%3};\n"
        : "+f"(c[0]), "+f"(c[1]), "+f"(c[2]), "+f"(c[3])
        : "r"(a[0]), "r"(a[1]), "r"(a[2]), "r"(a[3]), "r"(b[0]), "r"(b[1]));
}

__global__ __launch_bounds__(256) void fused_gemm_kernel(
    const float* __restrict__ x, const float* __restrict__ wi,
    const float* __restrict__ wr, const float* __restrict__ bias,
    float* __restrict__ out)
{
    __shared__ uint32_t As[128][36];      // [m][k], pad 4 -> conflict-free frags
    __shared__ uint32_t Bs[2][32][72];    // [km][k][n], pad 8 -> conflict-free

    const int tid = threadIdx.x;
    const int lane = tid & 31;
    const int wid = tid >> 5;
    const int warpM = wid & 3;            // 0..3 -> 32 rows each
    const int warpN = wid >> 2;           // 0..1 -> 32 cols each
    const int tileRow = blockIdx.y * 128;
    const int colBase = blockIdx.x * 64;

    float acc[2][2][4][4] = {};           // [km][mt][nt][c0..c3]

    for (int kk = 0; kk < KDIM; kk += 32) {
        const int phase = kk >> 8;        // 0: xp/Wi, 1: x/Wr
        const int kkL = kk & 255;
        const float* Amat = phase ? x : g_xp;
        const float* Bbase = phase ? wr : wi;

        // A tile: 128x32 = 1024 float4 over 256 threads (4 iters)
#pragma unroll
        for (int i = 0; i < 4; ++i) {
            int ii = i * 256 + tid;
            int m = ii >> 3, kq = ii & 7;
            int row = tileRow + m;
            float4 v = (row < NN)
                ? *(const float4*)(Amat + (size_t)row * FF + kkL + kq * 4)
                : make_float4(0.f, 0.f, 0.f, 0.f);
            uint4 u = make_uint4(f2tf32(v.x), f2tf32(v.y), f2tf32(v.z), f2tf32(v.w));
            *(uint4*)&As[m][kq * 4] = u;
        }
        // B tiles (both k matrices): 2x32x64 = 1024 float4
#pragma unroll
        for (int i = 0; i < 4; ++i) {
            int ii = i * 256 + tid;
            int km = ii >> 9, r = (ii >> 4) & 31, nq = ii & 15;
            const float* Bm = Bbase + (size_t)km * FF * FF;
            float4 v = *(const float4*)(Bm + (size_t)(kkL + r) * FF + colBase + nq * 4);
            uint4 u = make_uint4(f2tf32(v.x), f2tf32(v.y), f2tf32(v.z), f2tf32(v.w));
            *(uint4*)&Bs[km][r][nq * 4] = u;
        }
        __syncthreads();

#pragma unroll
        for (int ks = 0; ks < 4; ++ks) {
            const int k8 = ks * 8;
            uint32_t a[2][4];
#pragma unroll
            for (int mt = 0; mt < 2; ++mt) {
                int mrow = warpM * 32 + mt * 16 + (lane >> 2);
                a[mt][0] = As[mrow][k8 + (lane & 3)];
                a[mt][1] = As[mrow + 8][k8 + (lane & 3)];
                a[mt][2] = As[mrow][k8 + 4 + (lane & 3)];
                a[mt][3] = As[mrow + 8][k8 + 4 + (lane & 3)];
            }
            uint32_t b[2][4][2];
#pragma unroll
            for (int km = 0; km < 2; ++km)
#pragma unroll
                for (int nt = 0; nt < 4; ++nt) {
                    int ncol = warpN * 32 + nt * 8 + (lane >> 2);
                    b[km][nt][0] = Bs[km][k8 + (lane & 3)][ncol];
                    b[km][nt][1] = Bs[km][k8 + 4 + (lane & 3)][ncol];
                }
#pragma unroll
            for (int km = 0; km < 2; ++km)
#pragma unroll
                for (int mt = 0; mt < 2; ++mt)
#pragma unroll
                    for (int nt = 0; nt < 4; ++nt)
                        mma_tf32(acc[km][mt][nt], a[mt], b[km][nt]);
        }
        __syncthreads();
    }

    // Epilogue: out = x + relu(0.5*(relu(C0+b0)+relu(C1+b1)))
#pragma unroll
    for (int mt = 0; mt < 2; ++mt) {
#pragma unroll
        for (int nt = 0; nt < 4; ++nt) {
            const int col = colBase + warpN * 32 + nt * 8 + 2 * (lane & 3);
            const float bi00 = bias[col],      bi01 = bias[col + 1];
            const float bi10 = bias[FF + col], bi11 = bias[FF + col + 1];
            const int r0 = tileRow + warpM * 32 + mt * 16 + (lane >> 2);

            if (r0 < NN) {
                float2 xv = *(const float2*)(x + (size_t)r0 * FF + col);
                float u0 = fmaxf(acc[0][mt][nt][0] + bi00, 0.f);
                float v0 = fmaxf(acc[1][mt][nt][0] + bi10, 0.f);
                float u1 = fmaxf(acc[0][mt][nt][1] + bi01, 0.f);
                float v1 = fmaxf(acc[1][mt][nt][1] + bi11, 0.f);
                float2 o;
                o.x = xv.x + fmaxf(0.5f * (u0 + v0), 0.f);
                o.y = xv.y + fmaxf(0.5f * (u1 + v1), 0.f);
                *(float2*)(out + (size_t)r0 * FF + col) = o;
            }
            const int r1 = r0 + 8;
            if (r1 < NN) {
                float2 xv = *(const float2*)(x + (size_t)r1 * FF + col);
                float u0 = fmaxf(acc[0][mt][nt][2] + bi00, 0.f);
                float v0 = fmaxf(acc[1][mt][nt][2] + bi10, 0.f);
                float u1 = fmaxf(acc[0][mt][nt][3] + bi01, 0.f);
                float v1 = fmaxf(acc[1][mt][nt][3] + bi11, 0.f);
                float2 o;
                o.x = xv.x + fmaxf(0.5f * (u0 + v0), 0.f);
                o.y = xv.y + fmaxf(0.5f * (u1 + v1), 0.f);
                *(float2*)(out + (size_t)r1 * FF + col) = o;
            }
        }
    }
}

// ---------------------------------------------------------------------------
// launch
// ---------------------------------------------------------------------------
extern "C" void kernel_launch(void* const* d_in, const int* in_sizes, int n_in,
                              void* d_out, int out_size) {
    const float* x    = (const float*)d_in[0];
    const void* ei    = d_in[1];                 // edge_index [2,E], int32 or int64
    const float* wi   = (const float*)d_in[2];   // [K, F, F]
    const float* wr   = (const float*)d_in[3];   // [K, F, F]
    const float* bias = (const float*)d_in[4];   // [K, 1, F]
    float* out        = (float*)d_out;

    sniff_kernel<<<1, 32>>>((const int*)ei);
    zero_deg_kernel<<<(NN + 255) / 256, 256>>>();
    deg_kernel<<<(EE + 255) / 256, 256>>>(ei);
    dinv_kernel<<<(NN + 255) / 256, 256>>>();
    scan_kernel<<<1, 1024>>>();
    fill_csr_kernel<<<(EE + 255) / 256, 256>>>(ei);

    gather_xp_kernel<<<(NN * 32 + 255) / 256, 256>>>(x);

    dim3 ggrid(FF / 64, (NN + 127) / 128);   // (4, 391)
    fused_gemm_kernel<<<ggrid, 256>>>(x, wi, wr, bias, out);
}

// round 8
// speedup vs baseline: 2.5747x; 1.1837x over previous
#include <cuda_runtime.h>
#include <stdint.h>

#define NN 50000
#define EE 320000
#define FF 256
#define KK 2
#define KDIM 512
#define KITERS 16        // KDIM / 32

// Scratch (allocation-free rule: __device__ globals)
__device__ unsigned g_xptf[(size_t)NN * FF];           // tf32(A_hat @ x)
__device__ unsigned g_xtf[(size_t)NN * FF];            // tf32(x)
__device__ unsigned g_wtf[2][KK][FF][FF];              // tf32 weights: [phase][km][k][n], phase0=Wi, 1=Wr
__device__ int   g_degi[NN];
__device__ float g_dinv[NN];
__device__ int   g_rowstart[NN + 1];
__device__ int   g_cursor[NN];
__device__ int   g_csr_src[EE];
__device__ float g_csr_w[EE];
__device__ int   g_is64;

__device__ __forceinline__ unsigned f2tf32(float f) {
    unsigned r;
    asm("cvt.rna.tf32.f32 %0, %1;" : "=r"(r) : "f"(f));
    return r;
}

// ---------------------------------------------------------------------------
// dtype sniff
// ---------------------------------------------------------------------------
__global__ void sniff_kernel(const int* __restrict__ ei32) {
    if (threadIdx.x == 0) {
        int any = 0;
        for (int i = 0; i < 256; ++i) any |= ei32[2 * i + 1];
        g_is64 = (any == 0) ? 1 : 0;
    }
}

__device__ __forceinline__ int load_idx(const void* ei, int which, int e) {
    if (g_is64) return (int)((const long long*)ei)[(size_t)which * EE + e];
    return ((const int*)ei)[(size_t)which * EE + e];
}

// ---------------------------------------------------------------------------
// degree / dinv
// ---------------------------------------------------------------------------
__global__ void zero_deg_kernel() {
    int i = blockIdx.x * blockDim.x + threadIdx.x;
    if (i < NN) g_degi[i] = 0;
}

__global__ void deg_kernel(const void* __restrict__ ei) {
    int e = blockIdx.x * blockDim.x + threadIdx.x;
    if (e < EE) atomicAdd(&g_degi[load_idx(ei, 1, e)], 1);
}

__global__ void dinv_kernel() {
    int i = blockIdx.x * blockDim.x + threadIdx.x;
    if (i < NN) {
        int d = g_degi[i];
        g_dinv[i] = (d > 0) ? rsqrtf((float)d) : 0.0f;
    }
}

// ---------------------------------------------------------------------------
// convert weights + x to tf32
// ---------------------------------------------------------------------------
__global__ void cvt_w_kernel(const float* __restrict__ wi, const float* __restrict__ wr) {
    // 2 * K * F * F = 262144 elements, as float4: 65536
    int i = blockIdx.x * blockDim.x + threadIdx.x;
    if (i >= 65536) return;
    const int half = 32768;   // K*F*F/4
    const float* src = (i < half) ? wi : wr;
    int j = (i < half) ? i : i - half;
    float4 v = *(const float4*)(src + (size_t)j * 4);
    uint4 u = make_uint4(f2tf32(v.x), f2tf32(v.y), f2tf32(v.z), f2tf32(v.w));
    *(uint4*)(&g_wtf[0][0][0][0] + (size_t)i * 4) = u;
}

__global__ void cvt_x_kernel(const float* __restrict__ x) {
    size_t i = ((size_t)blockIdx.x * blockDim.x + threadIdx.x) * 4;
    if (i >= (size_t)NN * FF) return;
    float4 v = *(const float4*)(x + i);
    uint4 u = make_uint4(f2tf32(v.x), f2tf32(v.y), f2tf32(v.z), f2tf32(v.w));
    *(uint4*)(g_xtf + i) = u;
}

// ---------------------------------------------------------------------------
// Exclusive scan of degrees -> rowstart
// ---------------------------------------------------------------------------
#define SCAN_CH 49

__global__ __launch_bounds__(1024) void scan_kernel() {
    __shared__ int s[1024];
    const int t = threadIdx.x;
    const int base = t * SCAN_CH;
    int sum = 0;
#pragma unroll
    for (int i = 0; i < SCAN_CH; ++i) {
        int idx = base + i;
        if (idx < NN) sum += g_degi[idx];
    }
    s[t] = sum;
    __syncthreads();
    for (int off = 1; off < 1024; off <<= 1) {
        int v = (t >= off) ? s[t - off] : 0;
        __syncthreads();
        s[t] += v;
        __syncthreads();
    }
    int run = (t == 0) ? 0 : s[t - 1];
#pragma unroll
    for (int i = 0; i < SCAN_CH; ++i) {
        int idx = base + i;
        if (idx < NN) {
            g_rowstart[idx] = run;
            run += g_degi[idx];
            g_cursor[idx] = 0;
        }
    }
    if (t == 1023) g_rowstart[NN] = run;
}

__global__ void fill_csr_kernel(const void* __restrict__ ei) {
    int e = blockIdx.x * blockDim.x + threadIdx.x;
    if (e >= EE) return;
    int src = load_idx(ei, 0, e);
    int dst = load_idx(ei, 1, e);
    int pos = atomicAdd(&g_cursor[dst], 1);
    int idx = g_rowstart[dst] + pos;
    g_csr_src[idx] = src;
    g_csr_w[idx] = g_dinv[src] * g_dinv[dst];
}

// ---------------------------------------------------------------------------
// xp = A_hat @ x (fp32 accumulate), emitted as tf32. Warp per node, 2-edge unroll.
// ---------------------------------------------------------------------------
__global__ __launch_bounds__(256) void gather_xp_kernel(const float* __restrict__ x) {
    const int warp = (blockIdx.x * blockDim.x + threadIdx.x) >> 5;
    const int lane = threadIdx.x & 31;
    if (warp >= NN) return;
    const int n = warp;
    const int f = lane * 8;

    float4 a0 = make_float4(0.f, 0.f, 0.f, 0.f);
    float4 a1 = make_float4(0.f, 0.f, 0.f, 0.f);

    const int beg = g_rowstart[n];
    const int end = g_rowstart[n + 1];
    int e = beg;
    for (; e + 1 < end; e += 2) {
        const int s0 = g_csr_src[e],     s1 = g_csr_src[e + 1];
        const float w0 = g_csr_w[e],     w1 = g_csr_w[e + 1];
        const float* p0 = x + (size_t)s0 * FF + f;
        const float* p1 = x + (size_t)s1 * FF + f;
        float4 u0 = *(const float4*)(p0);
        float4 u1 = *(const float4*)(p0 + 4);
        float4 v0 = *(const float4*)(p1);
        float4 v1 = *(const float4*)(p1 + 4);
        a0.x += w0 * u0.x + w1 * v0.x;  a0.y += w0 * u0.y + w1 * v0.y;
        a0.z += w0 * u0.z + w1 * v0.z;  a0.w += w0 * u0.w + w1 * v0.w;
        a1.x += w0 * u1.x + w1 * v1.x;  a1.y += w0 * u1.y + w1 * v1.y;
        a1.z += w0 * u1.z + w1 * v1.z;  a1.w += w0 * u1.w + w1 * v1.w;
    }
    if (e < end) {
        const int s0 = g_csr_src[e];
        const float w0 = g_csr_w[e];
        const float* p0 = x + (size_t)s0 * FF + f;
        float4 u0 = *(const float4*)(p0);
        float4 u1 = *(const float4*)(p0 + 4);
        a0.x += w0 * u0.x; a0.y += w0 * u0.y; a0.z += w0 * u0.z; a0.w += w0 * u0.w;
        a1.x += w0 * u1.x; a1.y += w0 * u1.y; a1.z += w0 * u1.z; a1.w += w0 * u1.w;
    }

    unsigned* op = g_xptf + (size_t)n * FF + f;
    *(uint4*)(op)     = make_uint4(f2tf32(a0.x), f2tf32(a0.y), f2tf32(a0.z), f2tf32(a0.w));
    *(uint4*)(op + 4) = make_uint4(f2tf32(a1.x), f2tf32(a1.y), f2tf32(a1.z), f2tf32(a1.w));
}

// ---------------------------------------------------------------------------
// Fused tf32 GEMM + epilogue, cp.async 3-stage pipeline.
// Block: 128(M) x 128(N), BK=32, 512 threads (warp grid 4Mx4N, warp tile 32x32).
// Smem per stage: As[128][36] + Bs[2][32][136] (uint) = 53248 B; 3 stages.
// ---------------------------------------------------------------------------
#define AS_STRIDE 36
#define BS_STRIDE 136
#define AS_WORDS (128 * AS_STRIDE)                 // 4608
#define STAGE_WORDS (AS_WORDS + 2 * 32 * BS_STRIDE) // 4608 + 8704 = 13312
#define NSTAGES 3
#define GEMM_SMEM (NSTAGES * STAGE_WORDS * 4)

__device__ __forceinline__ void cp16(unsigned smaddr, const void* gptr, int valid) {
    asm volatile("cp.async.cg.shared.global [%0], [%1], 16, %2;"
                 :: "r"(smaddr), "l"(gptr), "r"(valid ? 16 : 0));
}
__device__ __forceinline__ void cp_commit() {
    asm volatile("cp.async.commit_group;");
}
template <int N>
__device__ __forceinline__ void cp_wait() {
    asm volatile("cp.async.wait_group %0;" :: "n"(N));
}

__device__ __forceinline__ void mma_tf32(float* c, const unsigned* a, const unsigned* b) {
    asm volatile(
        "mma.sync.aligned.m16n8k8.row.col.f32.tf32.tf32.f32 "
        "{%0,%1,%2,%3}, {%4,%5,%6,%7}, {%8,%9}, {%0,%1,%2,%3};\n"
        : "+f"(c[0]), "+f"(c[1]), "+f"(c[2]), "+f"(c[3])
        : "r"(a[0]), "r"(a[1]), "r"(a[2]), "r"(a[3]), "r"(b[0]), "r"(b[1]));
}

__global__ __launch_bounds__(512, 1) void fused_gemm_kernel(
    const float* __restrict__ x, const float* __restrict__ bias,
    float* __restrict__ out)
{
    extern __shared__ unsigned sm[];

    const int tid = threadIdx.x;
    const int lane = tid & 31;
    const int wid = tid >> 5;
    const int warpM = wid & 3;
    const int warpN = wid >> 2;
    const int tileRow = blockIdx.y * 128;
    const int colBase = blockIdx.x * 128;

    // Issue loads for iteration `it` into stage `st`
    auto issue = [&](int it, int st) {
        const int phase = it >> 3;              // 8 iters per phase
        const int kkL = (it & 7) * 32;
        const unsigned* Atf = phase ? g_xtf : g_xptf;
        unsigned* As = sm + st * STAGE_WORDS;
        unsigned* Bs = As + AS_WORDS;
        unsigned as_base = (unsigned)__cvta_generic_to_shared(As);
        unsigned bs_base = (unsigned)__cvta_generic_to_shared(Bs);
        // A: 128x32 = 1024 uint4, 512 threads -> 2 each
#pragma unroll
        for (int i = 0; i < 2; ++i) {
            int ii = i * 512 + tid;
            int m = ii >> 3, kq = ii & 7;
            int row = tileRow + m;
            int valid = row < NN;
            int rowc = valid ? row : 0;
            cp16(as_base + (m * AS_STRIDE + kq * 4) * 4,
                 Atf + (size_t)rowc * FF + kkL + kq * 4, valid);
        }
        // B: 2x32x128 = 2048 elems /4 = 512 uint4... per thread 4? 2048 uint4? No:
        // 2*32*128 = 8192 elems = 2048 uint4, 512 threads -> 4 each
#pragma unroll
        for (int i = 0; i < 4; ++i) {
            int ii = i * 512 + tid;
            int km = ii >> 10, r = (ii >> 5) & 31, nq = ii & 31;
            cp16(bs_base + (km * 32 * BS_STRIDE + r * BS_STRIDE + nq * 4) * 4,
                 &g_wtf[phase][km][kkL + r][colBase + nq * 4], 1);
        }
        cp_commit();
    };

    float acc[2][2][4][4] = {};   // [km][mt][nt][c]

    issue(0, 0);
    issue(1, 1);
    issue(2, 2);

    for (int it = 0; it < KITERS; ++it) {
        if (it < KITERS - 2)      cp_wait<2>();
        else if (it == KITERS - 2) cp_wait<1>();
        else                       cp_wait<0>();
        __syncthreads();

        const int st = it % NSTAGES;
        const unsigned* As = sm + st * STAGE_WORDS;
        const unsigned* Bs = As + AS_WORDS;

#pragma unroll
        for (int ks = 0; ks < 4; ++ks) {
            const int k8 = ks * 8;
            unsigned a[2][4];
#pragma unroll
            for (int mt = 0; mt < 2; ++mt) {
                int mrow = warpM * 32 + mt * 16 + (lane >> 2);
                const unsigned* r0 = As + mrow * AS_STRIDE + k8 + (lane & 3);
                const unsigned* r1 = As + (mrow + 8) * AS_STRIDE + k8 + (lane & 3);
                a[mt][0] = r0[0];
                a[mt][1] = r1[0];
                a[mt][2] = r0[4];
                a[mt][3] = r1[4];
            }
            unsigned b[2][4][2];
#pragma unroll
            for (int km = 0; km < 2; ++km)
#pragma unroll
                for (int nt = 0; nt < 4; ++nt) {
                    int ncol = warpN * 32 + nt * 8 + (lane >> 2);
                    const unsigned* bp = Bs + km * 32 * BS_STRIDE
                                         + (k8 + (lane & 3)) * BS_STRIDE + ncol;
                    b[km][nt][0] = bp[0];
                    b[km][nt][1] = bp[4 * BS_STRIDE];
                }
#pragma unroll
            for (int km = 0; km < 2; ++km)
#pragma unroll
                for (int mt = 0; mt < 2; ++mt)
#pragma unroll
                    for (int nt = 0; nt < 4; ++nt)
                        mma_tf32(acc[km][mt][nt], a[mt], b[km][nt]);
        }
        __syncthreads();
        if (it + NSTAGES < KITERS) issue(it + NSTAGES, st);
    }

    // Epilogue: out = x + relu(0.5*(relu(C0+b0)+relu(C1+b1)))
#pragma unroll
    for (int mt = 0; mt < 2; ++mt) {
#pragma unroll
        for (int nt = 0; nt < 4; ++nt) {
            const int col = colBase + warpN * 32 + nt * 8 + 2 * (lane & 3);
            const float bi00 = bias[col],      bi01 = bias[col + 1];
            const float bi10 = bias[FF + col], bi11 = bias[FF + col + 1];
            const int r0 = tileRow + warpM * 32 + mt * 16 + (lane >> 2);

            if (r0 < NN) {
                float2 xv = *(const float2*)(x + (size_t)r0 * FF + col);
                float u0 = fmaxf(acc[0][mt][nt][0] + bi00, 0.f);
                float v0 = fmaxf(acc[1][mt][nt][0] + bi10, 0.f);
                float u1 = fmaxf(acc[0][mt][nt][1] + bi01, 0.f);
                float v1 = fmaxf(acc[1][mt][nt][1] + bi11, 0.f);
                float2 o;
                o.x = xv.x + fmaxf(0.5f * (u0 + v0), 0.f);
                o.y = xv.y + fmaxf(0.5f * (u1 + v1), 0.f);
                *(float2*)(out + (size_t)r0 * FF + col) = o;
            }
            const int r1 = r0 + 8;
            if (r1 < NN) {
                float2 xv = *(const float2*)(x + (size_t)r1 * FF + col);
                float u0 = fmaxf(acc[0][mt][nt][2] + bi00, 0.f);
                float v0 = fmaxf(acc[1][mt][nt][2] + bi10, 0.f);
                float u1 = fmaxf(acc[0][mt][nt][3] + bi01, 0.f);
                float v1 = fmaxf(acc[1][mt][nt][3] + bi11, 0.f);
                float2 o;
                o.x = xv.x + fmaxf(0.5f * (u0 + v0), 0.f);
                o.y = xv.y + fmaxf(0.5f * (u1 + v1), 0.f);
                *(float2*)(out + (size_t)r1 * FF + col) = o;
            }
        }
    }
}

// ---------------------------------------------------------------------------
// launch
// ---------------------------------------------------------------------------
extern "C" void kernel_launch(void* const* d_in, const int* in_sizes, int n_in,
                              void* d_out, int out_size) {
    const float* x    = (const float*)d_in[0];
    const void* ei    = d_in[1];
    const float* wi   = (const float*)d_in[2];
    const float* wr   = (const float*)d_in[3];
    const float* bias = (const float*)d_in[4];
    float* out        = (float*)d_out;

    static int smem_set = 0;
    if (!smem_set) {
        cudaFuncSetAttribute(fused_gemm_kernel,
                             cudaFuncAttributeMaxDynamicSharedMemorySize, GEMM_SMEM);
        smem_set = 1;
    }

    sniff_kernel<<<1, 32>>>((const int*)ei);
    zero_deg_kernel<<<(NN + 255) / 256, 256>>>();
    deg_kernel<<<(EE + 255) / 256, 256>>>(ei);
    dinv_kernel<<<(NN + 255) / 256, 256>>>();
    scan_kernel<<<1, 1024>>>();
    fill_csr_kernel<<<(EE + 255) / 256, 256>>>(ei);

    cvt_w_kernel<<<(65536 + 255) / 256, 256>>>(wi, wr);
    cvt_x_kernel<<<(NN * FF / 4 + 255) / 256, 256>>>(x);
    gather_xp_kernel<<<(NN * 32 + 255) / 256, 256>>>(x);

    dim3 ggrid(FF / 128, (NN + 127) / 128);   // (2, 391)
    fused_gemm_kernel<<<ggrid, 512, GEMM_SMEM>>>(x, bias, out);
}